// round 9
// baseline (speedup 1.0000x reference)
#include <cuda_runtime.h>
#include <cuda_fp16.h>

#define N_USERS 50000
#define N_ITEMS 30000
#define N_ENT   100000
#define N_REL   8
#define E_KG    250000
#define E_UI    1000000
#define DIMF    128
#define ROWF    192      /* packed user row: 128 fp32 + 128 fp16 = 192 float slots */
#define KG_CNT  (N_REL*N_ENT)
#define TOT_CNT (KG_CNT + N_USERS)
#define KG_EDGE (N_REL*E_KG)
#define TOT_EDGE (KG_EDGE + E_UI)
#define SCAN_B  1024
#define NBLK    ((TOT_CNT + SCAN_B - 1)/SCAN_B)

// ---------------- scratch (static device globals; no allocation) ------------
__device__ float g_ent0[(size_t)N_ENT*DIMF];      // 51.2 MB fp32
__device__ float g_ent1[(size_t)N_ENT*DIMF];      // 51.2 MB fp32
__device__ float g_urow[(size_t)N_ITEMS*ROWF];    // 23.0 MB packed user rows
__device__ int2  g_cw[KG_EDGE];                   // 16 MB packed {col, w} per KG edge
__device__ int   g_cnt[TOT_CNT];
__device__ int   g_rowptr[TOT_CNT+1];
__device__ int   g_cursor[TOT_CNT];
__device__ int   g_col[TOT_EDGE];
__device__ int   g_bsum[NBLK];
__device__ float g_imean[DIMF];

__device__ __forceinline__ int kgrow(int d, int r) { return d*N_REL + r; }

__device__ __forceinline__ float4 ldh4(const __half* p) {
    uint2 u = __ldg((const uint2*)p);
    __half2 a = *(__half2*)&u.x, b = *(__half2*)&u.y;
    float2 f0 = __half22float2(a), f1 = __half22float2(b);
    return make_float4(f0.x, f0.y, f1.x, f1.y);
}
__device__ __forceinline__ void sth4(__half* p, float4 v) {
    __half2 a = __floats2half2_rn(v.x, v.y);
    __half2 b = __floats2half2_rn(v.z, v.w);
    uint2 u; u.x = *(unsigned*)&a; u.y = *(unsigned*)&b;
    *(uint2*)p = u;
}

// ---------------- CSR build -------------------------------------------------
__global__ void k_zero() {
    int i = blockIdx.x*blockDim.x + threadIdx.x;
    for (int t = i; t < TOT_CNT; t += gridDim.x*blockDim.x) g_cnt[t] = 0;
    if (i < DIMF) g_imean[i] = 0.f;
}

__global__ void k_count(const int* __restrict__ kg_dst, const int* __restrict__ ui_dst) {
    int tid = blockIdx.x*blockDim.x + threadIdx.x;
    if (tid < KG_EDGE) {
        int r = tid / E_KG;
        atomicAdd(&g_cnt[kgrow(__ldg(&kg_dst[tid]), r)], 1);
    } else if (tid < TOT_EDGE) {
        atomicAdd(&g_cnt[KG_CNT + __ldg(&ui_dst[tid - KG_EDGE])], 1);
    }
}

__global__ void k_scan1() {
    __shared__ int sh[SCAN_B];
    int i = blockIdx.x*SCAN_B + threadIdx.x;
    int v = (i < TOT_CNT) ? g_cnt[i] : 0;
    sh[threadIdx.x] = v;
    __syncthreads();
    #pragma unroll
    for (int off = 1; off < SCAN_B; off <<= 1) {
        int t = (threadIdx.x >= off) ? sh[threadIdx.x - off] : 0;
        __syncthreads();
        sh[threadIdx.x] += t;
        __syncthreads();
    }
    if (i < TOT_CNT) g_rowptr[i] = sh[threadIdx.x] - v;
    if (threadIdx.x == SCAN_B-1) g_bsum[blockIdx.x] = sh[SCAN_B-1];
}

__global__ void k_scan2() {
    __shared__ int sh[SCAN_B];
    int t = threadIdx.x;
    int v = (t < NBLK) ? g_bsum[t] : 0;
    sh[t] = v;
    __syncthreads();
    #pragma unroll
    for (int off = 1; off < SCAN_B; off <<= 1) {
        int u = (t >= off) ? sh[t - off] : 0;
        __syncthreads();
        sh[t] += u;
        __syncthreads();
    }
    if (t < NBLK) g_bsum[t] = sh[t] - v;
}

__global__ void k_scan3() {
    int i = blockIdx.x*blockDim.x + threadIdx.x;
    if (i < TOT_CNT) {
        int v = g_rowptr[i] + g_bsum[i / SCAN_B];
        g_rowptr[i] = v;
        g_cursor[i] = v;
    }
    if (i == TOT_CNT) g_rowptr[TOT_CNT] = TOT_EDGE;
}

// fill: writes col (for layer0/user) and packed {col, 1/deg} (for hop gathers)
__global__ void k_fill(const int* __restrict__ kg_src, const int* __restrict__ kg_dst,
                       const int* __restrict__ ui_src, const int* __restrict__ ui_dst) {
    int tid = blockIdx.x*blockDim.x + threadIdx.x;
    if (tid < KG_EDGE) {
        int r = tid / E_KG;
        int row = kgrow(__ldg(&kg_dst[tid]), r);
        int pos = atomicAdd(&g_cursor[row], 1);
        int c = __ldg(&kg_src[tid]);
        g_col[pos] = c;
        int deg = __ldg(&g_cnt[row]);
        float w = 1.f / (float)(deg > 1 ? deg : 1);
        g_cw[pos] = make_int2(c, __float_as_int(w));
    } else if (tid < TOT_EDGE) {
        int t = tid - KG_EDGE;
        int pos = atomicAdd(&g_cursor[KG_CNT + __ldg(&ui_dst[t])], 1);
        g_col[pos] = __ldg(&ui_src[t]);
    }
}

// ---------------- layer 0: flat edge loop + shared accumulation --------------
// warp per entity; half-warp per edge (16 dims each); relation recovered by
// comparing edge index against the entity's 9 prefetched rowptrs.
__global__ void k_layer0(const float* __restrict__ all_embed) {
    __shared__ float s_acc[8][DIMF];     // 8 warps/block * 128 slots = 4 KB
    int w = threadIdx.x >> 5;
    int lane = threadIdx.x & 31;
    int d = blockIdx.x*8 + w;
    #pragma unroll
    for (int k = 0; k < 4; k++) s_acc[w][lane*4 + k] = 0.f;
    __syncwarp();
    if (d >= N_ENT) return;

    int rp = (lane < 9) ? __ldg(&g_rowptr[d*N_REL + lane]) : 0;
    const unsigned FULL = 0xffffffffu;
    int rp0 = __shfl_sync(FULL, rp, 0);
    int rp1 = __shfl_sync(FULL, rp, 1);
    int rp2 = __shfl_sync(FULL, rp, 2);
    int rp3 = __shfl_sync(FULL, rp, 3);
    int rp4 = __shfl_sync(FULL, rp, 4);
    int rp5 = __shfl_sync(FULL, rp, 5);
    int rp6 = __shfl_sync(FULL, rp, 6);
    int rp7 = __shfl_sync(FULL, rp, 7);
    int rp8 = __shfl_sync(FULL, rp, 8);

    int dim  = lane & 15;
    int half = lane >> 4;
    int s = rp0, e = rp8;

    // flat edge loop, 2 edges per half-warp per iteration (4 LDGs in flight/warp)
    int j = s + half;
    for (; j + 2 < e; j += 4) {
        int ja = j, jb = j + 2;
        int ca = __ldg(&g_col[ja]);
        int cb = __ldg(&g_col[jb]);
        int ra = (ja>=rp1)+(ja>=rp2)+(ja>=rp3)+(ja>=rp4)+(ja>=rp5)+(ja>=rp6)+(ja>=rp7);
        int rb = (jb>=rp1)+(jb>=rp2)+(jb>=rp3)+(jb>=rp4)+(jb>=rp5)+(jb>=rp6)+(jb>=rp7);
        float va = __ldg(&all_embed[ca*DIMF + ra*16 + dim]);
        float vb = __ldg(&all_embed[cb*DIMF + rb*16 + dim]);
        atomicAdd(&s_acc[w][ra*16 + dim], va);
        atomicAdd(&s_acc[w][rb*16 + dim], vb);
    }
    if (j < e) {
        int c = __ldg(&g_col[j]);
        int r = (j>=rp1)+(j>=rp2)+(j>=rp3)+(j>=rp4)+(j>=rp5)+(j>=rp6)+(j>=rp7);
        float v = __ldg(&all_embed[c*DIMF + r*16 + dim]);
        atomicAdd(&s_acc[w][r*16 + dim], v);
    }
    __syncwarp();

    // epilogue: each lane owns 4 consecutive slots; divide by relation degree
    float4 o;
    {
        int idx = lane*4;           // all 4 slots share one relation (idx>>4 const across k)
        int r = idx >> 4;
        int degs = __shfl_sync(FULL, rp, r);
        int dege = __shfl_sync(FULL, rp, r + 1);
        float inv = 1.f / fmaxf((float)(dege - degs), 1.f);
        o.x = s_acc[w][idx + 0] * inv;
        o.y = s_acc[w][idx + 1] * inv;
        o.z = s_acc[w][idx + 2] * inv;
        o.w = s_acc[w][idx + 3] * inv;
    }
    *(float4*)&g_ent0[d*DIMF + lane*4] = o;
}

// ---- flat weighted KG gather with packed {col,w}: one 8B load per edge -----
__device__ __forceinline__ float4 kg_gather(const float* __restrict__ src,
                                            int s, int e, int lane) {
    float4 a0 = make_float4(0.f,0.f,0.f,0.f);
    float4 a1 = make_float4(0.f,0.f,0.f,0.f);
    int j = s;
    for (; j + 3 < e; j += 4) {
        int2 p0 = __ldg(&g_cw[j]),   p1 = __ldg(&g_cw[j+1]);
        int2 p2 = __ldg(&g_cw[j+2]), p3 = __ldg(&g_cw[j+3]);
        float4 v0 = __ldg((const float4*)&src[p0.x*DIMF + lane*4]);
        float4 v1 = __ldg((const float4*)&src[p1.x*DIMF + lane*4]);
        float4 v2 = __ldg((const float4*)&src[p2.x*DIMF + lane*4]);
        float4 v3 = __ldg((const float4*)&src[p3.x*DIMF + lane*4]);
        float w0 = __int_as_float(p0.y), w1 = __int_as_float(p1.y);
        float w2 = __int_as_float(p2.y), w3 = __int_as_float(p3.y);
        a0.x += w0*v0.x; a0.y += w0*v0.y; a0.z += w0*v0.z; a0.w += w0*v0.w;
        a1.x += w1*v1.x; a1.y += w1*v1.y; a1.z += w1*v1.z; a1.w += w1*v1.w;
        a0.x += w2*v2.x; a0.y += w2*v2.y; a0.z += w2*v2.z; a0.w += w2*v2.w;
        a1.x += w3*v3.x; a1.y += w3*v3.y; a1.z += w3*v3.z; a1.w += w3*v3.w;
    }
    for (; j < e; j++) {
        int2 p = __ldg(&g_cw[j]);
        float w = __int_as_float(p.y);
        float4 v = __ldg((const float4*)&src[p.x*DIMF + lane*4]);
        a0.x += w*v.x; a0.y += w*v.y; a0.z += w*v.z; a0.w += w*v.w;
    }
    return make_float4(a0.x+a1.x, a0.y+a1.y, a0.z+a1.z, a0.w+a1.w);
}

// ---------------- hop1: ent1[d] = sum_r mean_r(ent0[src]) --------------------
__global__ void k_hop1() {
    int d = blockIdx.x*(blockDim.x/32) + (threadIdx.x >> 5);
    if (d >= N_ENT) return;
    int lane = threadIdx.x & 31;
    int s = __ldg(&g_rowptr[d*N_REL]);
    int e = __ldg(&g_rowptr[(d+1)*N_REL]);
    float4 acc = kg_gather(g_ent0, s, e, lane);
    *(float4*)&g_ent1[d*DIMF + lane*4] = acc;
}

// ---------------- hop2 (items) + item_out + packed user row + item_mean -----
__global__ void k_hop2_items(const float* __restrict__ cf, float* __restrict__ out_item) {
    __shared__ float s_im[DIMF];
    int tid = threadIdx.x;
    if (tid < DIMF) s_im[tid] = 0.f;
    __syncthreads();

    int d = blockIdx.x*(blockDim.x/32) + (tid >> 5);
    int lane = tid & 31;
    if (d < N_ITEMS) {
        int s = __ldg(&g_rowptr[d*N_REL]);
        int e = __ldg(&g_rowptr[(d+1)*N_REL]);
        float4 acc = kg_gather(g_ent1, s, e, lane);
        int o = d*DIMF + lane*4;
        const float4 e0 = *(const float4*)&g_ent0[o];
        const float4 e1 = *(const float4*)&g_ent1[o];
        float4 res;
        res.x = acc.x + e0.x + e1.x;
        res.y = acc.y + e0.y + e1.y;
        res.z = acc.z + e0.z + e1.z;
        res.w = acc.w + e0.w + e1.w;
        const float4 c = __ldg((const float4*)&cf[(size_t)(N_USERS + d)*DIMF + lane*4]);
        float4 oi;
        oi.x = res.x + c.x; oi.y = res.y + c.y; oi.z = res.z + c.z; oi.w = res.w + c.w;
        *(float4*)&out_item[o] = oi;
        float* row = &g_urow[(size_t)d*ROWF];
        *(float4*)&row[lane*4] = res;
        sth4((__half*)&row[DIMF] + lane*4, c);
        atomicAdd(&s_im[lane*4 + 0], res.x);
        atomicAdd(&s_im[lane*4 + 1], res.y);
        atomicAdd(&s_im[lane*4 + 2], res.z);
        atomicAdd(&s_im[lane*4 + 3], res.w);
    }
    __syncthreads();
    if (tid < DIMF) atomicAdd(&g_imean[tid], s_im[tid] * (1.f / N_ITEMS));
}

// ---------------- user aggregation + fused attention epilogue ---------------
__global__ void k_user(const float* __restrict__ cf, float* __restrict__ out_user) {
    int u = blockIdx.x*(blockDim.x/32) + (threadIdx.x >> 5);
    if (u >= N_USERS) return;
    int lane = threadIdx.x & 31;
    int base = KG_CNT + u;
    int s = __ldg(&g_rowptr[base]), e = __ldg(&g_rowptr[base+1]);
    float4 a0 = make_float4(0.f,0.f,0.f,0.f);
    float4 a1 = make_float4(0.f,0.f,0.f,0.f);
    float4 b0 = make_float4(0.f,0.f,0.f,0.f);
    float4 b1 = make_float4(0.f,0.f,0.f,0.f);
    int j = s;
    for (; j + 3 < e; j += 4) {
        const float* r0 = &g_urow[(size_t)__ldg(&g_col[j])  *ROWF];
        const float* r1 = &g_urow[(size_t)__ldg(&g_col[j+1])*ROWF];
        const float* r2 = &g_urow[(size_t)__ldg(&g_col[j+2])*ROWF];
        const float* r3 = &g_urow[(size_t)__ldg(&g_col[j+3])*ROWF];
        float4 x0 = __ldg((const float4*)&r0[lane*4]);
        float4 x1 = __ldg((const float4*)&r1[lane*4]);
        float4 x2 = __ldg((const float4*)&r2[lane*4]);
        float4 x3 = __ldg((const float4*)&r3[lane*4]);
        float4 y0 = ldh4((const __half*)&r0[DIMF] + lane*4);
        float4 y1 = ldh4((const __half*)&r1[DIMF] + lane*4);
        float4 y2 = ldh4((const __half*)&r2[DIMF] + lane*4);
        float4 y3 = ldh4((const __half*)&r3[DIMF] + lane*4);
        a0.x += x0.x; a0.y += x0.y; a0.z += x0.z; a0.w += x0.w;
        a1.x += x1.x; a1.y += x1.y; a1.z += x1.z; a1.w += x1.w;
        a0.x += x2.x; a0.y += x2.y; a0.z += x2.z; a0.w += x2.w;
        a1.x += x3.x; a1.y += x3.y; a1.z += x3.z; a1.w += x3.w;
        b0.x += y0.x; b0.y += y0.y; b0.z += y0.z; b0.w += y0.w;
        b1.x += y1.x; b1.y += y1.y; b1.z += y1.z; b1.w += y1.w;
        b0.x += y2.x; b0.y += y2.y; b0.z += y2.z; b0.w += y2.w;
        b1.x += y3.x; b1.y += y3.y; b1.z += y3.z; b1.w += y3.w;
    }
    for (; j < e; j++) {
        const float* r0 = &g_urow[(size_t)__ldg(&g_col[j])*ROWF];
        float4 x0 = __ldg((const float4*)&r0[lane*4]);
        float4 y0 = ldh4((const __half*)&r0[DIMF] + lane*4);
        a0.x += x0.x; a0.y += x0.y; a0.z += x0.z; a0.w += x0.w;
        b0.x += y0.x; b0.y += y0.y; b0.z += y0.z; b0.w += y0.w;
    }
    float inv = 1.f / fmaxf((float)(e - s), 1.f);
    float4 uf  = make_float4((a0.x+a1.x)*inv, (a0.y+a1.y)*inv, (a0.z+a1.z)*inv, (a0.w+a1.w)*inv);
    float4 uf0 = make_float4((b0.x+b1.x)*inv, (b0.y+b1.y)*inv, (b0.z+b1.z)*inv, (b0.w+b1.w)*inv);
    const float4 ucf = __ldg((const float4*)&cf[(size_t)u*DIMF + lane*4]);
    const float4 im  = *(const float4*)&g_imean[lane*4];

    float ua = uf.x*ucf.x + uf.y*ucf.y + uf.z*ucf.z + uf.w*ucf.w;
    float ma = im.x*ucf.x + im.y*ucf.y + im.z*ucf.z + im.w*ucf.w;
    ua += __shfl_xor_sync(0xffffffffu, ua, 1);
    ua += __shfl_xor_sync(0xffffffffu, ua, 2);
    ma += __shfl_xor_sync(0xffffffffu, ma, 1);
    ma += __shfl_xor_sync(0xffffffffu, ma, 2);
    ua = fmaxf(ua, 0.f) + 1e-10f;
    ma = fmaxf(ma, 0.f) + 1e-8f;
    float att = fmaxf(ua/ma - 1.f, 0.f) + 0.01f;   // K_ATT = 1.0
    float score = tanhf(att);

    float4 o;
    o.x = score*uf.x + uf0.x + ucf.x;
    o.y = score*uf.y + uf0.y + ucf.y;
    o.z = score*uf.z + uf0.z + ucf.z;
    o.w = score*uf.w + uf0.w + ucf.w;
    *(float4*)&out_user[(size_t)u*DIMF + lane*4] = o;
}

// ---------------- launch ----------------------------------------------------
extern "C" void kernel_launch(void* const* d_in, const int* in_sizes, int n_in,
                              void* d_out, int out_size) {
    const float* all_embed    = (const float*)d_in[0];
    const float* all_embed_cf = (const float*)d_in[1];
    const int*   kg_src       = (const int*)d_in[2];
    const int*   kg_dst       = (const int*)d_in[3];
    const int*   ui_src_item  = (const int*)d_in[4];
    const int*   ui_dst_user  = (const int*)d_in[5];
    float* out = (float*)d_out;
    float* out_item = out;                        // [N_ITEMS, 128]
    float* out_user = out + (size_t)N_ITEMS*DIMF; // [N_USERS, 128]

    const int T = 256;
    // CSR build
    k_zero<<<1024, T>>>();
    k_count<<<(TOT_EDGE + T - 1)/T, T>>>(kg_dst, ui_dst_user);
    k_scan1<<<NBLK, SCAN_B>>>();
    k_scan2<<<1, SCAN_B>>>();
    k_scan3<<<(TOT_CNT + T)/T, T>>>();
    k_fill<<<(TOT_EDGE + T - 1)/T, T>>>(kg_src, kg_dst, ui_src_item, ui_dst_user);

    // KG propagation
    int entWarpBlocks  = (N_ENT   + (T/32) - 1) / (T/32);
    int itemWarpBlocks = (N_ITEMS + (T/32) - 1) / (T/32);
    k_layer0<<<entWarpBlocks, T>>>(all_embed);
    k_hop1<<<entWarpBlocks, T>>>();
    k_hop2_items<<<itemWarpBlocks, T>>>(all_embed_cf, out_item);

    // user epilogue
    int userWarpBlocks = (N_USERS + (T/32) - 1) / (T/32);
    k_user<<<userWarpBlocks, T>>>(all_embed_cf, out_user);
}